// round 1
// baseline (speedup 1.0000x reference)
#include <cuda_runtime.h>

#define NC 32
#define NSTEPS 32
#define DDIM 30
#define TPB 256
#define PPT 4

// tab layout: tab[cell*32 + lane] -> lane l always hits bank (2l, 2l+1) pair.
// Conflict-free-by-construction regardless of data-dependent cell values.
__global__ __launch_bounds__(TPB) void cpab_kernel(
    const float* __restrict__ points,
    const float* __restrict__ theta,
    const float* __restrict__ basis,
    float* __restrict__ out,
    int n_points)
{
    __shared__ float2 tab[NC * 32];
    __shared__ float ea_s[NC];
    __shared__ float bp_s[NC];

    const int t   = blockIdx.y;
    const int tid = threadIdx.x;

    // ---- build per-theta table (32 cells) ----
    if (tid < NC) {
        const int c = tid;
        const float* __restrict__ th = theta + t * DDIM;
        const float* __restrict__ ba = basis + (2 * c) * DDIM;
        const float* __restrict__ bb = basis + (2 * c + 1) * DDIM;
        float a = 0.0f, b = 0.0f;
        #pragma unroll
        for (int j = 0; j < DDIM; j++) {
            a = fmaf(ba[j], th[j], a);
            b = fmaf(bb[j], th[j], b);
        }
        const float dT = 1.0f / (float)NSTEPS;
        float ad = dT * a;
        float bd = dT * b;
        // phi(ad) = expm1(ad)/ad with stable small-ad branch (matches reference)
        float phi = (fabsf(ad) < 1e-6f) ? (1.0f + 0.5f * ad) : (expm1f(ad) / ad);
        ea_s[c] = expf(ad);
        bp_s[c] = bd * phi;
    }
    __syncthreads();

    // replicate across 32 lane slots
    #pragma unroll
    for (int i = tid; i < NC * 32; i += TPB) {
        int c = i >> 5;
        tab[i] = make_float2(ea_s[c], bp_s[c]);
    }
    __syncthreads();

    const int lane = tid & 31;
    const float2* __restrict__ mytab = tab + lane;

    // ---- integrate PPT points per thread (independent chains for ILP) ----
    const int pbase = blockIdx.x * (TPB * PPT) + tid;

    float x[PPT];
    #pragma unroll
    for (int k = 0; k < PPT; k++)
        x[k] = points[pbase + k * TPB];

    #pragma unroll 4
    for (int s = 0; s < NSTEPS; s++) {
        #pragma unroll
        for (int k = 0; k < PPT; k++) {
            // cell = clip(floor(x*NC), 0, NC-1); float-clamp then trunc is equivalent
            float cf = fminf(fmaxf(x[k] * (float)NC, 0.0f), (float)(NC - 1));
            int c = (int)cf;
            float2 T = mytab[c << 5];          // tab[c*32 + lane]
            x[k] = fmaf(T.x, x[k], T.y);
        }
    }

    float* __restrict__ o = out + (size_t)t * n_points;
    #pragma unroll
    for (int k = 0; k < PPT; k++)
        o[pbase + k * TPB] = x[k];
}

extern "C" void kernel_launch(void* const* d_in, const int* in_sizes, int n_in,
                              void* d_out, int out_size) {
    const float* points = (const float*)d_in[0];   // [1, n_points]
    const float* theta  = (const float*)d_in[1];   // [8, 30]
    const float* basis  = (const float*)d_in[2];   // [64, 30]
    float* out = (float*)d_out;                    // [8, 1, n_points]

    const int n_points = in_sizes[0];              // NDIM == 1
    const int n_theta  = in_sizes[1] / DDIM;

    dim3 grid(n_points / (TPB * PPT), n_theta);
    cpab_kernel<<<grid, TPB>>>(points, theta, basis, out, n_points);
}